// round 1
// baseline (speedup 1.0000x reference)
#include <cuda_runtime.h>
#include <math.h>

// Problem dims (fixed for this problem instance)
#define B_   128
#define T_   500
#define NI_  256
#define N_   256
#define M_   (B_*T_)          // 64000 rows of the input GEMM

// Scratch for xw = x @ w_in : [B, T, N] fp32 (device global: allocation-free rule)
__device__ float g_xw[(size_t)M_ * N_];

// ---------------------------------------------------------------------------
// Packed fp32x2 helpers (Blackwell FFMA2: 2x fp32 FMA per lane per inst)
// ---------------------------------------------------------------------------
#define FFMA2(d, a, b, c) \
    asm("fma.rn.f32x2 %0, %1, %2, %3;" : "=l"(d) : "l"(a), "l"(b), "l"(c))
#define PACK2(d, s) \
    asm("mov.b64 %0, {%1, %1};" : "=l"(d) : "f"(s))

// ---------------------------------------------------------------------------
// Kernel 1: xw[m][n] = sum_k x[m][k] * w_in[k][n]   (M=64000, K=256, N=256)
// BM=64, BN=128, BK=32, 256 threads, 4m x 8n microtile via f32x2 pairs.
// Accumulation over k is strictly ascending (matches reference dot ordering
// as closely as a tiled kernel can).
// ---------------------------------------------------------------------------
__global__ void __launch_bounds__(256, 2)
gemm_xw(const float* __restrict__ A, const float* __restrict__ W)
{
    __shared__ float As[32][68];    // transposed [k][m], padded for b128 LDS
    __shared__ float Bs[32][128];   // natural    [k][n]

    const int tid = threadIdx.x;
    const int bm  = blockIdx.x * 64;
    const int bn  = blockIdx.y * 128;
    const int tn  = tid & 15;       // 8 n-columns each
    const int tm  = tid >> 4;       // 4 m-rows each

    unsigned long long acc[4][4];
#pragma unroll
    for (int i = 0; i < 4; i++)
#pragma unroll
        for (int j = 0; j < 4; j++) acc[i][j] = 0ull;

    for (int kt = 0; kt < NI_; kt += 32) {
        // Load A tile (64 rows x 32 k) transposed into As[k][m]
#pragma unroll
        for (int i = 0; i < 2; i++) {
            int fl  = tid * 2 + i;          // 0..511
            int row = fl >> 3;              // 0..63
            int c4  = (fl & 7) << 2;        // k offset 0..28
            float4 v = *(const float4*)(A + (size_t)(bm + row) * NI_ + kt + c4);
            As[c4 + 0][row] = v.x;
            As[c4 + 1][row] = v.y;
            As[c4 + 2][row] = v.z;
            As[c4 + 3][row] = v.w;
        }
        // Load B tile (32 k-rows x 128 n)
#pragma unroll
        for (int i = 0; i < 4; i++) {
            int fl  = tid + (i << 8);
            int row = fl >> 5;              // 0..31
            int c4  = (fl & 31) << 2;       // 0..124
            *(float4*)&Bs[row][c4] =
                *(const float4*)(W + (size_t)(kt + row) * N_ + bn + c4);
        }
        __syncthreads();

#pragma unroll
        for (int k = 0; k < 32; k++) {
            float4 av = *(const float4*)&As[k][tm << 2];
            unsigned long long a2[4];
            PACK2(a2[0], av.x); PACK2(a2[1], av.y);
            PACK2(a2[2], av.z); PACK2(a2[3], av.w);

            const ulonglong2* bp = (const ulonglong2*)&Bs[k][tn << 3];
            ulonglong2 b01 = bp[0], b23 = bp[1];
            unsigned long long b2[4];
            b2[0] = b01.x; b2[1] = b01.y; b2[2] = b23.x; b2[3] = b23.y;

#pragma unroll
            for (int i = 0; i < 4; i++)
#pragma unroll
                for (int j = 0; j < 4; j++)
                    FFMA2(acc[i][j], a2[i], b2[j], acc[i][j]);
        }
        __syncthreads();
    }

    // Epilogue: write 4 rows x 8 cols per thread
#pragma unroll
    for (int i = 0; i < 4; i++) {
        float2 f[4];
#pragma unroll
        for (int j = 0; j < 4; j++) f[j] = *(float2*)&acc[i][j];
        float4 lo = make_float4(f[0].x, f[0].y, f[1].x, f[1].y);
        float4 hi = make_float4(f[2].x, f[2].y, f[3].x, f[3].y);
        float* cp = g_xw + (size_t)(bm + (tm << 2) + i) * N_ + bn + (tn << 3);
        *(float4*)cp       = lo;
        *(float4*)(cp + 4) = hi;
    }
}

// ---------------------------------------------------------------------------
// Kernel 2: persistent per-batch LSNN scan.
// CTA = one batch row, thread = one neuron. 500 serial steps, 1 bar/step.
// w_rec rows [0,224) live in smem (224 KB); rows [224,256) live in registers
// (32 regs/thread, selected by a ballot bitmask from warp 7).
// Active presynaptic neurons tracked as deterministic per-warp segmented lists
// (byte offsets), double-buffered so one __syncthreads per step suffices.
// ---------------------------------------------------------------------------
#define WROWS 224
#define SCAN_SMEM (WROWS*256*4 + 2*224*4 + 16*4 + 2*4)   // 231240 bytes

__global__ void __launch_bounds__(256, 1)
lsnn_scan(const float* __restrict__ w_rec,
          const float* __restrict__ z0,  const float* __restrict__ v0,
          const float* __restrict__ a0,  const float* __restrict__ lsd0,
          float* __restrict__ out, float decay_v, float decay_a)
{
    extern __shared__ float sm[];
    float*    w_sm  = sm;                               // [224][256]
    int*      actL  = (int*)(sm + WROWS * 256);         // [2][224] byte-offsets
    int*      cntL  = actL + 2 * 224;                   // [2][8]
    unsigned* maskH = (unsigned*)(cntL + 16);           // [2]

    const int b    = blockIdx.x;
    const int n    = threadIdx.x;
    const int w    = n >> 5;
    const int lane = n & 31;

    // Cooperative load of low weight rows into smem (float4)
    {
        const float4* src = (const float4*)w_rec;
        float4*       dst = (float4*)w_sm;
#pragma unroll
        for (int i = 0; i < (WROWS * 256 / 4) / 256; i++)
            dst[n + i * 256] = src[n + i * 256];
    }
    // High rows -> registers (compile-time indexed only)
    float wreg[32];
#pragma unroll
    for (int j = 0; j < 32; j++) wreg[j] = w_rec[(WROWS + j) * 256 + n];
#pragma unroll
    for (int j = 0; j < 32; j++)            // mask diagonal (self-connection)
        if (n == WROWS + j) wreg[j] = 0.f;
    __syncthreads();
    if (n < WROWS) w_sm[n * 256 + n] = 0.f; // mask diagonal in smem rows

    float z_self = z0[b * N_ + n];
    float v      = v0[b * N_ + n];
    float a      = a0[b * N_ + n];
    float lsd    = lsd0[b * N_ + n];

    // Build initial active lists (from z0) into buffer 0
    {
        unsigned m = __ballot_sync(0xffffffffu, z_self != 0.f);
        if (w < 7) {
            if (lane == 0) cntL[w] = __popc(m);
            if (z_self != 0.f) {
                int r = __popc(m & ((1u << lane) - 1u));
                actL[w * 32 + r] = n << 10;    // byte offset of row n
            }
        } else if (lane == 0) maskH[0] = m;
    }
    __syncthreads();

    const float omdv = 1.f - decay_v;
    const float omda = 1.f - decay_a;
    const char*  wp   = (const char*)w_sm + (n << 2);
    const float* xwp  = g_xw + (size_t)b * T_ * N_ + n;
    const size_t TBN  = (size_t)T_ * B_ * N_;

    float xw_cur = __ldcs(xwp);

    for (int t = 0; t < T_; t++) {
        const int rb = t & 1, wb = rb ^ 1;
        float xw_next = (t + 1 < T_) ? __ldcs(xwp + (size_t)(t + 1) * N_) : 0.f;

        // ---- recurrent input: sum of active rows (two chains for ILP) ----
        float acc0 = 0.f, acc1 = 0.f;
#pragma unroll 1
        for (int sw = 0; sw < 7; sw++) {
            const int  c   = cntL[rb * 8 + sw];
            const int* lst = actL + rb * 224 + sw * 32;
            int j = 0;
            for (; j + 1 < c; j += 2) {
                int o0 = lst[j], o1 = lst[j + 1];
                acc0 += *(const float*)(wp + o0);
                acc1 += *(const float*)(wp + o1);
            }
            if (j < c) acc0 += *(const float*)(wp + lst[j]);
        }
        {
            const unsigned mh = maskH[rb];
#pragma unroll
            for (int j = 0; j < 32; j += 2) {
                if (mh & (1u <<  j))      acc0 += wreg[j];
                if (mh & (1u << (j + 1))) acc1 += wreg[j + 1];
            }
        }
        const float i_in = __fadd_rn(xw_cur, __fadd_rn(acc0, acc1));

        // ---- neuron dynamics (mirror reference expression structure) ----
        float new_a = __fadd_rn(__fmul_rn(decay_a, a), __fmul_rn(omda, z_self));
        float thr   = __fadd_rn(0.03f, __fmul_rn(new_a, 1.8f));
        float new_v = __fadd_rn(
                        __fadd_rn(__fmul_rn(decay_v, v), __fmul_rn(omdv, i_in)),
                        __fmul_rn(-thr, z_self));
        float v_sc  = __fdiv_rn(__fadd_rn(new_v, -thr), thr);
        float zf    = (v_sc > 0.f) ? 1.f : 0.f;
        if (lsd < 2.f) zf = 0.f;                       // refractory
        float new_lsd = __fmul_rn(__fadd_rn(lsd, 1.f), __fadd_rn(1.f, -zf));

        // ---- outputs [4, T, B, N] : z, v, thr, v_sc ----
        const size_t ob = ((size_t)t * B_ + b) * N_ + n;
        __stcs(out + ob,           zf);
        __stcs(out + TBN + ob,     new_v);
        __stcs(out + 2 * TBN + ob, thr);
        __stcs(out + 3 * TBN + ob, v_sc);

        // ---- rebuild active lists for next step into buffer wb ----
        unsigned m = __ballot_sync(0xffffffffu, zf != 0.f);
        if (w < 7) {
            if (lane == 0) cntL[wb * 8 + w] = __popc(m);
            if (zf != 0.f) {
                int r = __popc(m & ((1u << lane) - 1u));
                actL[wb * 224 + w * 32 + r] = n << 10;
            }
        } else if (lane == 0) maskH[wb] = m;

        z_self = zf; v = new_v; a = new_a; lsd = new_lsd;
        xw_cur = xw_next;
        __syncthreads();
    }
}

// ---------------------------------------------------------------------------
// Launcher (graph-capturable: kernel launches only, no allocs, no syncs)
// ---------------------------------------------------------------------------
extern "C" void kernel_launch(void* const* d_in, const int* in_sizes, int n_in,
                              void* d_out, int out_size)
{
    const float* x     = (const float*)d_in[0];
    const float* w_in  = (const float*)d_in[1];
    const float* w_rec = (const float*)d_in[2];
    const float* z0    = (const float*)d_in[3];
    const float* v0    = (const float*)d_in[4];
    const float* a0    = (const float*)d_in[5];
    const float* lsd0  = (const float*)d_in[6];
    float* out = (float*)d_out;

    const float decay_v = expf(-1.0f / 20.0f);   // TAU = 20
    const float decay_a = expf(-1.0f / 20.0f);   // TAU_ADAPT = 20

    // Opt-in smem for the scan kernel (idempotent; not a stream op)
    cudaFuncSetAttribute(lsnn_scan,
                         cudaFuncAttributeMaxDynamicSharedMemorySize,
                         SCAN_SMEM);

    dim3 g1(M_ / 64, N_ / 128);        // 1000 x 2 tiles
    gemm_xw<<<g1, 256>>>(x, w_in);

    lsnn_scan<<<B_, 256, SCAN_SMEM>>>(w_rec, z0, v0, a0, lsd0, out,
                                      decay_v, decay_a);
}

// round 2
// speedup vs baseline: 1.6488x; 1.6488x over previous
#include <cuda_runtime.h>
#include <math.h>

// Problem dims (fixed)
#define B_   128
#define T_   500
#define NI_  256
#define N_   256
#define M_   (B_*T_)
#define TBN_ ((size_t)T_*B_*N_)

// xw scratch, m-pair interleaved: ULL index p*256+n holds (xw[2p][n], xw[2p+1][n])
__device__ unsigned long long g_xw[(size_t)M_ * N_ / 2];

// Packed fp32x2 helpers
#define FFMA2(d, a, b, c) \
    asm("fma.rn.f32x2 %0, %1, %2, %3;" : "=l"(d) : "l"(a), "l"(b), "l"(c))
#define PACK2(d, s) \
    asm("mov.b64 %0, {%1, %1};" : "=l"(d) : "f"(s))

// ===========================================================================
// Kernel 1: xw = x @ w_in. BM=128, BN=256, BK=16, 256 thr, 8x16 microtile.
// 2-stage pipeline: A via LDG->regs->STS (transposed, pad 132), B via cp.async.
// k-accumulation strictly ascending.
// ===========================================================================
#define ASTRIDE 132
#define ASZ (2*16*ASTRIDE)          // floats
#define BSZ (2*16*256)              // floats
#define GEMM_SMEM ((ASZ + BSZ) * 4) // 49664 bytes

__global__ void __launch_bounds__(256, 1)
gemm_xw(const float* __restrict__ A, const float* __restrict__ W)
{
    extern __shared__ float gsm[];
    float* As = gsm;          // [2][16][132]  (k-major, m inner)
    float* Bs = gsm + ASZ;    // [2][16][256]

    const int t  = threadIdx.x;
    const int bm = blockIdx.x << 7;
    const int tm = t >> 4, tn = t & 15;
    const int m0 = tm << 3;

    // A load mapping: i in {0,1}: id=t+256i -> am=id>>2 (row), ak=(id&3)*4
    const int amr[2] = { (t) >> 2, (t + 256) >> 2 };
    const int akc[2] = { (t & 3) << 2, (t & 3) << 2 };
    // B load mapping: i in {0..3}: id=t+256i -> bk=id>>6, bn=(id&63)*4

    unsigned long long acc[4][16];
#pragma unroll
    for (int e = 0; e < 4; e++)
#pragma unroll
        for (int j = 0; j < 16; j++) acc[e][j] = 0ull;

    float4 ra[2];

    // ---- prologue: tile 0 ----
#pragma unroll
    for (int i = 0; i < 2; i++)
        ra[i] = *(const float4*)(A + (size_t)(bm + amr[i]) * NI_ + akc[i]);
#pragma unroll
    for (int i = 0; i < 4; i++) {
        int id = t + (i << 8), bk = id >> 6, bn = (id & 63) << 2;
        unsigned dst = (unsigned)__cvta_generic_to_shared(Bs + bk * 256 + bn);
        const float* src = W + (size_t)bk * N_ + bn;
        asm volatile("cp.async.cg.shared.global [%0], [%1], 16;" :: "r"(dst), "l"(src));
    }
    asm volatile("cp.async.commit_group;");
#pragma unroll
    for (int i = 0; i < 2; i++) {
        As[(akc[i] + 0) * ASTRIDE + amr[i]] = ra[i].x;
        As[(akc[i] + 1) * ASTRIDE + amr[i]] = ra[i].y;
        As[(akc[i] + 2) * ASTRIDE + amr[i]] = ra[i].z;
        As[(akc[i] + 3) * ASTRIDE + amr[i]] = ra[i].w;
    }
    asm volatile("cp.async.wait_group 0;");
    __syncthreads();

    for (int kt = 0; kt < 16; kt++) {
        const int st = kt & 1;
        if (kt < 15) {
#pragma unroll
            for (int i = 0; i < 2; i++)
                ra[i] = *(const float4*)(A + (size_t)(bm + amr[i]) * NI_
                                           + (kt + 1) * 16 + akc[i]);
#pragma unroll
            for (int i = 0; i < 4; i++) {
                int id = t + (i << 8), bk = id >> 6, bn = (id & 63) << 2;
                unsigned dst = (unsigned)__cvta_generic_to_shared(
                    Bs + (st ^ 1) * (16 * 256) + bk * 256 + bn);
                const float* src = W + (size_t)((kt + 1) * 16 + bk) * N_ + bn;
                asm volatile("cp.async.cg.shared.global [%0], [%1], 16;"
                             :: "r"(dst), "l"(src));
            }
            asm volatile("cp.async.commit_group;");
        }

        // ---- compute stage st ----
        const float* as = As + st * (16 * ASTRIDE);
        const float* bs = Bs + st * (16 * 256);
#pragma unroll
        for (int k = 0; k < 16; k++) {
            ulonglong2 aA = *(const ulonglong2*)(as + k * ASTRIDE + m0);
            ulonglong2 aB = *(const ulonglong2*)(as + k * ASTRIDE + m0 + 4);
            unsigned long long am4[4] = { aA.x, aA.y, aB.x, aB.y };
#pragma unroll
            for (int c = 0; c < 4; c++) {
                float4 bv = *(const float4*)(bs + k * 256 + (c << 6) + (tn << 2));
                unsigned long long b0, b1, b2, b3;
                PACK2(b0, bv.x); PACK2(b1, bv.y);
                PACK2(b2, bv.z); PACK2(b3, bv.w);
#pragma unroll
                for (int e = 0; e < 4; e++) {
                    FFMA2(acc[e][4*c+0], am4[e], b0, acc[e][4*c+0]);
                    FFMA2(acc[e][4*c+1], am4[e], b1, acc[e][4*c+1]);
                    FFMA2(acc[e][4*c+2], am4[e], b2, acc[e][4*c+2]);
                    FFMA2(acc[e][4*c+3], am4[e], b3, acc[e][4*c+3]);
                }
            }
        }
        if (kt == 15) break;

#pragma unroll
        for (int i = 0; i < 2; i++) {
            float* ad = As + (st ^ 1) * (16 * ASTRIDE);
            ad[(akc[i] + 0) * ASTRIDE + amr[i]] = ra[i].x;
            ad[(akc[i] + 1) * ASTRIDE + amr[i]] = ra[i].y;
            ad[(akc[i] + 2) * ASTRIDE + amr[i]] = ra[i].z;
            ad[(akc[i] + 3) * ASTRIDE + amr[i]] = ra[i].w;
        }
        asm volatile("cp.async.wait_group 0;");
        __syncthreads();
    }

    // ---- epilogue: pair-interleaved store, no unpack ----
    unsigned long long* op = g_xw;
    const int pbase = (bm + m0) >> 1;
#pragma unroll
    for (int e = 0; e < 4; e++) {
        size_t prow = (size_t)(pbase + e) * 256;
#pragma unroll
        for (int c = 0; c < 4; c++) {
            int ncol = (c << 6) + (tn << 2);
            ulonglong2 s0, s1;
            s0.x = acc[e][4*c+0]; s0.y = acc[e][4*c+1];
            s1.x = acc[e][4*c+2]; s1.y = acc[e][4*c+3];
            *(ulonglong2*)(op + prow + ncol)     = s0;
            *(ulonglong2*)(op + prow + ncol + 2) = s1;
        }
    }
}

// ===========================================================================
// Kernel 2: persistent per-batch LSNN scan. CTA = batch, thread = neuron.
// w_rec rows [0,224) + one zero sentinel row in smem; rows [224,256) in regs.
// Flat active list (sentinel-padded to int4 granularity), 2 barriers/step.
// ===========================================================================
#define WROWS 224
#define SENT  (224 << 10)
#define SCAN_SMEM (225*256*4 + 480*4 + 16*4 + 2*4 + 2*4)   // 232400 B

__global__ void __launch_bounds__(256, 1)
lsnn_scan(const float* __restrict__ w_rec,
          const float* __restrict__ z0,  const float* __restrict__ v0,
          const float* __restrict__ a0,  const float* __restrict__ lsd0,
          float* __restrict__ out, float decay_v, float decay_a)
{
    extern __shared__ float sm[];
    float*    w_sm  = sm;                          // [225][256], row 224 = zeros
    int*      flatL = (int*)(sm + 225 * 256);      // [2][240]
    int*      cntS  = flatL + 480;                 // [2][8]
    unsigned* maskH = (unsigned*)(cntS + 16);      // [2]
    int*      totS  = (int*)(maskH + 2);           // [2]

    const int b    = blockIdx.x;
    const int n    = threadIdx.x;
    const int w    = n >> 5;
    const int lane = n & 31;

    // weights rows 0..223 -> smem
    {
        const float4* src = (const float4*)w_rec;
        float4*       dst = (float4*)w_sm;
#pragma unroll
        for (int i = 0; i < 56; i++) dst[n + (i << 8)] = src[n + (i << 8)];
    }
    // rows 224..255 -> regs, diag masked
    float wreg[32];
#pragma unroll
    for (int j = 0; j < 32; j++) wreg[j] = w_rec[(WROWS + j) * 256 + n];
#pragma unroll
    for (int j = 0; j < 32; j++)
        if (n == WROWS + j) wreg[j] = 0.f;
    w_sm[224 * 256 + n] = 0.f;                    // zero sentinel row
    if (n < 16) cntS[n] = 0;                      // incl. slot 7 of both buffers
    __syncthreads();
    if (n < WROWS) w_sm[n * 256 + n] = 0.f;       // diag mask (needs bar below)

    float z_self = z0[b * N_ + n];
    float v      = v0[b * N_ + n];
    float a      = a0[b * N_ + n];
    float lsd    = lsd0[b * N_ + n];

    // initial list build (buffer 0)
    unsigned mB = __ballot_sync(0xffffffffu, z_self != 0.f);
    if (w < 7) { if (lane == 0) cntS[w] = __popc(mB); }
    else if (lane == 0) maskH[0] = mB;
    __syncthreads();
    {
        int4 cA = *(const int4*)&cntS[0];
        int4 cB = *(const int4*)&cntS[4];
        if (w < 7) {
            int start = 0;
            if (w > 0) start += cA.x; if (w > 1) start += cA.y;
            if (w > 2) start += cA.z; if (w > 3) start += cA.w;
            if (w > 4) start += cB.x; if (w > 5) start += cB.y;
            if (z_self != 0.f) {
                int r = __popc(mB & ((1u << lane) - 1u));
                flatL[start + r] = n << 10;
            }
        } else {
            int tt = cA.x + cA.y + cA.z + cA.w + cB.x + cB.y + cB.z;
            if (lane < 8) flatL[tt + lane] = SENT;
            if (lane == 0) totS[0] = tt;
        }
    }

    const float omdv = 1.f - decay_v;
    const float omda = 1.f - decay_a;
    const char*  wpn = (const char*)w_sm + (n << 2);
    const float* xwb = (const float*)g_xw;
    const int    mb0 = b * T_;
    const int    twon = n << 1;

    int m00 = mb0;
    float xw_cur = __ldcs(xwb + (((size_t)(m00 >> 1)) << 9) + twon + (m00 & 1));
    __syncthreads();

    for (int t = 0; t < T_; t++) {
        const int rb = t & 1, wb = rb ^ 1;

        float xw_next = 0.f;
        if (t + 1 < T_) {
            int mn = mb0 + t + 1;
            xw_next = __ldcs(xwb + (((size_t)(mn >> 1)) << 9) + twon + (mn & 1));
        }

        const int      tot = totS[rb];
        const unsigned mh  = maskH[rb];
        const int*     fl  = flatL + rb * 240;
        int4 o = *(const int4*)fl;

        float acc0 = 0.f, acc1 = 0.f, acc2 = 0.f, acc3 = 0.f;
        // register-held high rows (fills list-load latency)
#pragma unroll
        for (int j = 0; j < 32; j += 4) {
            if (mh & (1u <<  j))      acc0 += wreg[j];
            if (mh & (1u << (j + 1))) acc1 += wreg[j + 1];
            if (mh & (1u << (j + 2))) acc2 += wreg[j + 2];
            if (mh & (1u << (j + 3))) acc3 += wreg[j + 3];
        }
        // flat gather, offsets prefetched one int4 ahead
        for (int j = 0; j < tot; j += 4) {
            int4 onx = *(const int4*)(fl + j + 4);
            acc0 += *(const float*)(wpn + o.x);
            acc1 += *(const float*)(wpn + o.y);
            acc2 += *(const float*)(wpn + o.z);
            acc3 += *(const float*)(wpn + o.w);
            o = onx;
        }
        const float i_in = __fadd_rn(xw_cur,
            __fadd_rn(__fadd_rn(acc0, acc1), __fadd_rn(acc2, acc3)));

        // dynamics (identical op structure to the passing R1 kernel)
        float new_a = __fadd_rn(__fmul_rn(decay_a, a), __fmul_rn(omda, z_self));
        float thr   = __fadd_rn(0.03f, __fmul_rn(new_a, 1.8f));
        float new_v = __fadd_rn(
                        __fadd_rn(__fmul_rn(decay_v, v), __fmul_rn(omdv, i_in)),
                        __fmul_rn(-thr, z_self));
        float v_sc  = __fdividef(__fadd_rn(new_v, -thr), thr);  // sign-exact
        float zf    = (v_sc > 0.f) ? 1.f : 0.f;
        if (lsd < 2.f) zf = 0.f;
        float new_lsd = __fmul_rn(__fadd_rn(lsd, 1.f), __fadd_rn(1.f, -zf));

        // phase 1: publish counts / high mask
        unsigned m = __ballot_sync(0xffffffffu, zf != 0.f);
        if (w < 7) { if (lane == 0) cntS[wb * 8 + w] = __popc(m); }
        else if (lane == 0) maskH[wb] = m;
        __syncthreads();

        // outputs [4, T, B, N] (independent of phase 2)
        const size_t ob = ((size_t)t * B_ + b) * N_ + n;
        __stcs(out + ob,            zf);
        __stcs(out + TBN_ + ob,     new_v);
        __stcs(out + 2 * TBN_ + ob, thr);
        __stcs(out + 3 * TBN_ + ob, v_sc);

        // phase 2: prefix + flat write + sentinels
        {
            int4 cA = *(const int4*)&cntS[wb * 8];
            int4 cB = *(const int4*)&cntS[wb * 8 + 4];
            if (w < 7) {
                int start = 0;
                if (w > 0) start += cA.x; if (w > 1) start += cA.y;
                if (w > 2) start += cA.z; if (w > 3) start += cA.w;
                if (w > 4) start += cB.x; if (w > 5) start += cB.y;
                if (zf != 0.f) {
                    int r = __popc(m & ((1u << lane) - 1u));
                    flatL[wb * 240 + start + r] = n << 10;
                }
            } else {
                int tt = cA.x + cA.y + cA.z + cA.w + cB.x + cB.y + cB.z;
                if (lane < 8) flatL[wb * 240 + tt + lane] = SENT;
                if (lane == 0) totS[wb] = tt;
            }
        }

        z_self = zf; v = new_v; a = new_a; lsd = new_lsd;
        xw_cur = xw_next;
        __syncthreads();
    }
}

// ---------------------------------------------------------------------------
// Launcher (graph-capturable)
// ---------------------------------------------------------------------------
extern "C" void kernel_launch(void* const* d_in, const int* in_sizes, int n_in,
                              void* d_out, int out_size)
{
    const float* x     = (const float*)d_in[0];
    const float* w_in  = (const float*)d_in[1];
    const float* w_rec = (const float*)d_in[2];
    const float* z0    = (const float*)d_in[3];
    const float* v0    = (const float*)d_in[4];
    const float* a0    = (const float*)d_in[5];
    const float* lsd0  = (const float*)d_in[6];
    float* out = (float*)d_out;

    const float decay_v = expf(-1.0f / 20.0f);
    const float decay_a = expf(-1.0f / 20.0f);

    cudaFuncSetAttribute(gemm_xw,
                         cudaFuncAttributeMaxDynamicSharedMemorySize, GEMM_SMEM);
    cudaFuncSetAttribute(lsnn_scan,
                         cudaFuncAttributeMaxDynamicSharedMemorySize, SCAN_SMEM);

    gemm_xw<<<M_ / 128, 256, GEMM_SMEM>>>(x, w_in);
    lsnn_scan<<<B_, 256, SCAN_SMEM>>>(w_rec, z0, v0, a0, lsd0, out,
                                      decay_v, decay_a);
}